// round 6
// baseline (speedup 1.0000x reference)
#include <cuda_runtime.h>

#define H 128
#define W 128
#define HW 16384

// ---------------- device scratch (no allocations allowed) ----------------
__device__ float g_off[4 * 10 * HW];       // conv1 output, channels 0..9 only
__device__ float g_mu[20];                 // GN1 mean  per (b, group0..4)
__device__ float g_rstd[20];               // GN1 rstd
__device__ float g_ymap[4 * 9 * HW];       // clipped y coordinate per (b,k,h,w)
__device__ float g_pre[4 * 64 * HW];       // conv2 output pre-GN
__device__ float g_part[4 * 128 * 16 * 2]; // per-(b,h,group) partial sum/sumsq
__device__ unsigned long long g_wD[576 * 64]; // conv2 weights, transposed AND
                                              // duplicated: g_wD[ci*9+k][co] = {w,w}

#define FMA2(a, v, wt) asm("fma.rn.f32x2 %0, %1, %2, %0;" : "+l"(a) : "l"(v), "l"(wt))

// ------- kernel 1: 3x3 conv 64->10ch, 2 rows/thread  (+ weight prep) -----
// grid (65, 4): bx<64 -> conv rows 2bx,2bx+1 ; bx==64 -> build g_wD
__global__ void __launch_bounds__(128) k_conv1(const float* __restrict__ x,
                                               const float* __restrict__ w_off,
                                               const float* __restrict__ b_off,
                                               const float* __restrict__ w_dsc) {
    int bx = blockIdx.x, b = blockIdx.y;
    int tid = threadIdx.x;

    if (bx == 64) {                        // weight transpose + f32x2 dup
        int t = b * 128 + tid;             // 0..511
        for (int i = t; i < 36864; i += 512) {
            int co = i / 576, r = i - co * 576;  // r = ci*9+k
            float wv = w_dsc[i];
            unsigned long long d;
            asm("mov.b64 %0,{%1,%1};" : "=l"(d) : "f"(wv));
            g_wD[r * 64 + co] = d;
        }
        return;
    }

    __shared__ float ws[64 * 90]; // [cin][t(9)][c(10)] channel pairs 8B aligned
    for (int i = tid; i < 64 * 90; i += 128) {
        int cin = i / 90, r = i - cin * 90;
        int t = r / 10, c = r - t * 10;
        ws[i] = w_off[(c * 64 + cin) * 9 + t];
    }
    __syncthreads();

    int h0 = bx * 2;                       // rows h0, h0+1
    int w = tid;

    unsigned long long acc0[5], acc1[5];
#pragma unroll
    for (int j = 0; j < 5; j++) {
        float b0 = b_off[2 * j], b1 = b_off[2 * j + 1];
        unsigned long long bb;
        asm("mov.b64 %0,{%1,%2};" : "=l"(bb) : "f"(b0), "f"(b1));
        acc0[j] = bb; acc1[j] = bb;
    }

    const float* xb = x + b * 64 * HW;
    for (int cin = 0; cin < 64; ++cin) {
        float r[4][3];                     // rows h0-1 .. h0+2
#pragma unroll
        for (int dy = 0; dy < 4; ++dy) {
            int hy = h0 - 1 + dy;
            bool hv = (hy >= 0 && hy < H);
            const float* row = xb + cin * HW + hy * W;
            r[dy][0] = (hv && w >= 1)       ? row[w - 1] : 0.f;
            r[dy][1] = hv                    ? row[w]     : 0.f;
            r[dy][2] = (hv && w <= W - 2)    ? row[w + 1] : 0.f;
        }
        const unsigned long long* wp2 = (const unsigned long long*)(ws + cin * 90);
#pragma unroll
        for (int t = 0; t < 9; t++) {
            int dy = t / 3, dx = t - dy * 3;
            unsigned long long v0, v1;
            asm("mov.b64 %0,{%1,%1};" : "=l"(v0) : "f"(r[dy][dx]));
            asm("mov.b64 %0,{%1,%1};" : "=l"(v1) : "f"(r[dy + 1][dx]));
#pragma unroll
            for (int j = 0; j < 5; j++) {
                unsigned long long wpair = wp2[t * 5 + j];
                FMA2(acc0[j], v0, wpair);
                FMA2(acc1[j], v1, wpair);
            }
        }
    }
    int base0 = b * 10 * HW + h0 * W + w;
#pragma unroll
    for (int j = 0; j < 5; j++) {
        union { unsigned long long u; float2 f; } c0, c1;
        c0.u = acc0[j]; c1.u = acc1[j];
        g_off[base0 + (2 * j) * HW]         = c0.f.x;
        g_off[base0 + (2 * j + 1) * HW]     = c0.f.y;
        g_off[base0 + W + (2 * j) * HW]     = c1.f.x;
        g_off[base0 + W + (2 * j + 1) * HW] = c1.f.y;
    }
}

// ---------------- kernel 2: GN1 stats (groups of 2 channels) -------------
__global__ void __launch_bounds__(256) k_gn1_stats() {
    int bg = blockIdx.x;          // 0..19 : b*5+g
    int b = bg / 5, g = bg - b * 5;
    const float* p = g_off + (b * 10 + 2 * g) * HW;
    float s = 0.f, q = 0.f;
    for (int i = threadIdx.x; i < 2 * HW; i += 256) {
        float v = p[i];
        s += v; q += v * v;
    }
    __shared__ float rs[256], rq[256];
    int tid = threadIdx.x;
    rs[tid] = s; rq[tid] = q;
    __syncthreads();
    for (int st = 128; st > 0; st >>= 1) {
        if (tid < st) { rs[tid] += rs[tid + st]; rq[tid] += rq[tid + st]; }
        __syncthreads();
    }
    if (tid == 0) {
        float mu = rs[0] / 32768.f;
        float var = rq[0] / 32768.f - mu * mu;
        g_mu[bg] = mu;
        g_rstd[bg] = rsqrtf(var + 1e-5f);
    }
}

// --------- kernel 3: normalize + tanh + cumsum -> y coordinate map -------
__global__ void __launch_bounds__(256) k_offsets(const float* __restrict__ gam,
                                                 const float* __restrict__ bet) {
    int pix = blockIdx.x * 256 + threadIdx.x;   // 65536 pixels
    int b = pix >> 14, hw = pix & 16383;
    int h = hw >> 7;

    float t[10];
#pragma unroll
    for (int c = 0; c < 10; c++) {
        float v = g_off[(b * 10 + c) * HW + hw];
        int g = c >> 1;
        v = (v - g_mu[b * 5 + g]) * g_rstd[b * 5 + g];
        t[c] = tanhf(v * gam[c] + bet[c]);
    }
    float yn[9];
    yn[3] = t[3];
    yn[2] = t[2] + yn[3];
    yn[1] = t[1] + yn[2];
    yn[0] = t[0] + yn[1];
    yn[4] = 0.f;
    yn[5] = t[5];
    yn[6] = yn[5] + t[6];
    yn[7] = yn[6] + t[7];
    yn[8] = yn[7] + t[8];
#pragma unroll
    for (int k = 0; k < 9; k++) {
        float yc = fminf(fmaxf((float)h + yn[k], 0.f), 127.f);
        g_ymap[((b * 9 + k) << 14) + hw] = yc;
    }
}

// --------- kernel 4: fused sampling + 9x1 strided conv, pipelined --------
// grid (h=128, b=4), 128 threads, 4 CTAs/SM -> whole grid in ONE wave.
// thread: oct = tid>>4 -> 8 output channels, wg = tid&15 -> 16 w.
// Chunks of 4 cin, DOUBLE-BUFFERED: gather LDGs for chunk c+1 are issued
// before each ci-GEMM block of chunk c (staged in regs), interp+STS after.
__global__ void __launch_bounds__(128, 4) k_fused(const float* __restrict__ x,
                                                  const float* __restrict__ b_dsc) {
    __shared__ float buf[2 * 4608];          // two 4x1152 slabs (swizzled)
    __shared__ int2  tab[1152];              // packed sampling metadata
    __shared__ float redA[128], redB[128], qA[128], qB[128];

    int h = blockIdx.x, b = blockIdx.y;
    int tid = threadIdx.x;
    int oct = tid >> 4, wg = tid & 15;

    // phase A: pack metadata. Each thread writes/reads ONLY its own 9 entries
    // (e = tid + 128j), so no barrier needed around tab accesses.
    // entry: bits[0:14) addr0 = y0*128+xw, [14:25) sstore = k*128+swz(w),
    //        bit 25 = (y0 < 127), plus wy as float
    for (int e = tid; e < 1152; e += 128) {
        int k = e >> 7, w = e & 127;
        float yc = g_ymap[((b * 9 + k) << 14) + (h << 7) + w];
        int y0 = (int)yc;                    // yc in [0,127] -> trunc == floor
        float wy = yc - (float)y0;
        int xw = min(127, max(0, w + k - 4));
        int u = w >> 2;
        int sw = (((u ^ ((u >> 3) & 3)) << 2) | (w & 3));
        int pk = ((y0 << 7) + xw) | ((k * 128 + sw) << 14)
               | ((y0 < 127) ? (1 << 25) : 0);
        int2 t2; t2.x = pk; t2.y = __float_as_int(wy);
        tab[e] = t2;
    }

    // prologue: fill buf[0] with chunk 0 (cin 0..3)
    {
        const float* xb0 = x + ((b * 64) << 14);
        for (int e = tid; e < 1152; e += 128) {
            int2 pw = tab[e];
            int a0 = pw.x & 16383;
            int ss = (pw.x >> 14) & 2047;
            int dy = (pw.x >> 18) & 128;
            float wy = __int_as_float(pw.y);
            const float* p0 = xb0 + a0;
            const float* p1 = p0 + dy;
#pragma unroll
            for (int ci = 0; ci < 4; ci++) {
                float v0 = p0[ci << 14];
                float v1 = p1[ci << 14];
                buf[ss + ci * 1152] = fmaf(wy, v1 - v0, v0);
            }
        }
    }
    __syncthreads();

    unsigned long long acc[32];              // [co(8)][wpair(4)]
#pragma unroll
    for (int i = 0; i < 32; i++) acc[i] = 0ull;

    // swizzled 16B-line indices for this thread's 16 w
    int u0 = wg * 2;
    int su0 = u0 ^ ((u0 >> 3) & 3);
    int u1 = u0 + 1;
    int su1 = u1 ^ ((u1 >> 3) & 3);

#pragma unroll 1
    for (int c4 = 0; c4 < 16; ++c4) {        // cin chunks of 4
        float* bcur = buf + (c4 & 1) * 4608;
        float* bnxt = buf + ((c4 & 1) ^ 1) * 4608;
        const float* xbn = x + ((b * 64 + (c4 + 1) * 4) << 14);
        bool dofill = (c4 < 15);

#pragma unroll 1
        for (int cib = 0; cib < 4; ++cib) {
            // ---- issue gather loads for next chunk, batch {3,2,2,2} ----
            int start = (cib == 0) ? 0 : (2 * cib + 1);
            int cnt = (cib == 0) ? 3 : 2;
            float f0[12], f1[12];
            int ssv[3]; float wyv[3];
#pragma unroll
            for (int t = 0; t < 3; ++t) {
                if (dofill && t < cnt) {
                    int2 pw = tab[(start + t) * 128 + tid];
                    int a0 = pw.x & 16383;
                    ssv[t] = (pw.x >> 14) & 2047;
                    int dy = (pw.x >> 18) & 128;
                    wyv[t] = __int_as_float(pw.y);
                    const float* p0 = xbn + a0;
                    const float* p1 = p0 + dy;
#pragma unroll
                    for (int ci = 0; ci < 4; ci++) {
                        f0[t * 4 + ci] = p0[ci << 14];
                        f1[t * 4 + ci] = p1[ci << 14];
                    }
                }
            }

            // ---- GEMM block: one cin of current chunk, all 9 k ----
            const ulonglong2* wrow =
                (const ulonglong2*)g_wD + ((c4 * 4 + cib) * 9) * 32 + oct * 4;
            const float* srow = bcur + cib * 1152;
#pragma unroll
            for (int k = 0; k < 9; ++k) {
                ulonglong2 wd0 = __ldg(wrow + k * 32 + 0); // co 8oct+0,+1
                ulonglong2 wd1 = __ldg(wrow + k * 32 + 1); // co +2,+3
                ulonglong2 wd2 = __ldg(wrow + k * 32 + 2); // co +4,+5
                ulonglong2 wd3 = __ldg(wrow + k * 32 + 3); // co +6,+7
                const ulonglong2* sk = (const ulonglong2*)(srow + k * 128);
                ulonglong2 va = sk[su0];
                ulonglong2 vb = sk[su1];
                FMA2(acc[0],  va.x, wd0.x); FMA2(acc[1],  va.y, wd0.x);
                FMA2(acc[2],  vb.x, wd0.x); FMA2(acc[3],  vb.y, wd0.x);
                FMA2(acc[4],  va.x, wd0.y); FMA2(acc[5],  va.y, wd0.y);
                FMA2(acc[6],  vb.x, wd0.y); FMA2(acc[7],  vb.y, wd0.y);
                FMA2(acc[8],  va.x, wd1.x); FMA2(acc[9],  va.y, wd1.x);
                FMA2(acc[10], vb.x, wd1.x); FMA2(acc[11], vb.y, wd1.x);
                FMA2(acc[12], va.x, wd1.y); FMA2(acc[13], va.y, wd1.y);
                FMA2(acc[14], vb.x, wd1.y); FMA2(acc[15], vb.y, wd1.y);
                FMA2(acc[16], va.x, wd2.x); FMA2(acc[17], va.y, wd2.x);
                FMA2(acc[18], vb.x, wd2.x); FMA2(acc[19], vb.y, wd2.x);
                FMA2(acc[20], va.x, wd2.y); FMA2(acc[21], va.y, wd2.y);
                FMA2(acc[22], vb.x, wd2.y); FMA2(acc[23], vb.y, wd2.y);
                FMA2(acc[24], va.x, wd3.x); FMA2(acc[25], va.y, wd3.x);
                FMA2(acc[26], vb.x, wd3.x); FMA2(acc[27], vb.y, wd3.x);
                FMA2(acc[28], va.x, wd3.y); FMA2(acc[29], va.y, wd3.y);
                FMA2(acc[30], vb.x, wd3.y); FMA2(acc[31], vb.y, wd3.y);
            }

            // ---- interp + STS for the staged batch ----
#pragma unroll
            for (int t = 0; t < 3; ++t) {
                if (dofill && t < cnt) {
                    float* sp = bnxt + ssv[t];
#pragma unroll
                    for (int ci = 0; ci < 4; ci++)
                        sp[ci * 1152] = fmaf(wyv[t],
                                             f1[t * 4 + ci] - f0[t * 4 + ci],
                                             f0[t * 4 + ci]);
                }
            }
        }
        __syncthreads();
    }

    // epilogue: bias, store pre-GN, deterministic partial stats.
    // c 0..3 -> GN group 2*oct ; c 4..7 -> group 2*oct+1
    float sA = 0.f, qa = 0.f, sB = 0.f, qb = 0.f;
#pragma unroll
    for (int c = 0; c < 8; ++c) {
        int co = oct * 8 + c;
        float bias = b_dsc[co];
        float o[8];
#pragma unroll
        for (int p = 0; p < 4; ++p) {
            union { unsigned long long u; float2 f; } cv;
            cv.u = acc[c * 4 + p];
            o[2 * p]     = cv.f.x + bias;
            o[2 * p + 1] = cv.f.y + bias;
        }
        float* outp = g_pre + ((b * 64 + co) << 14) + (h << 7) + wg * 8;
        float4 s0; s0.x = o[0]; s0.y = o[1]; s0.z = o[2]; s0.w = o[3];
        float4 s1; s1.x = o[4]; s1.y = o[5]; s1.z = o[6]; s1.w = o[7];
        *(float4*)(outp) = s0;
        *(float4*)(outp + 4) = s1;
        float ls = 0.f, lq = 0.f;
#pragma unroll
        for (int p = 0; p < 8; ++p) { ls += o[p]; lq += o[p] * o[p]; }
        if (c < 4) { sA += ls; qa += lq; } else { sB += ls; qb += lq; }
    }
    redA[tid] = sA; redB[tid] = sB; qA[tid] = qa; qB[tid] = qb;
    __syncthreads();
    if (tid < 16) {                         // tid = group g; oct o = g>>1
        int o = tid >> 1;
        const float* rs = (tid & 1) ? redB : redA;
        const float* rq = (tid & 1) ? qB : qA;
        float ss = 0.f, qq = 0.f;
#pragma unroll
        for (int i = 0; i < 16; ++i) {
            ss += rs[o * 16 + i];
            qq += rq[o * 16 + i];
        }
        int idx = (((b << 7) + h) * 16 + tid) * 2;
        g_part[idx] = ss;
        g_part[idx + 1] = qq;
    }
}

// --------- kernel 5: GN2 reduce (per block, own group) + norm + relu -----
__global__ void __launch_bounds__(256) k_final(const float* __restrict__ gam,
                                               const float* __restrict__ bet,
                                               float* __restrict__ out) {
    int tid = threadIdx.x;
    int i0 = blockIdx.x * 1024;             // block covers 1024 floats (one b,c)
    int b = i0 >> 20;
    int c = (i0 >> 14) & 63;
    int g = c >> 2;

    // reduce this group's 128 per-h partials (deterministic fixed order)
    __shared__ float red[8];
    float s = 0.f, q = 0.f;
    if (tid < 128) {
        int idx = (((b << 7) + tid) * 16 + g) * 2;
        s = g_part[idx];
        q = g_part[idx + 1];
    }
#pragma unroll
    for (int o = 16; o; o >>= 1) {
        s += __shfl_down_sync(0xffffffffu, s, o);
        q += __shfl_down_sync(0xffffffffu, q, o);
    }
    if (tid < 128 && (tid & 31) == 0) {
        red[(tid >> 5) * 2] = s;
        red[(tid >> 5) * 2 + 1] = q;
    }
    __syncthreads();
    if (tid == 0) {
        float ss = red[0] + red[2] + red[4] + red[6];
        float qq = red[1] + red[3] + red[5] + red[7];
        float mu = ss / 65536.f;
        float var = qq / 65536.f - mu * mu;
        red[0] = mu;
        red[1] = rsqrtf(var + 1e-5f);
    }
    __syncthreads();
    float mu = red[0], rs = red[1];

    int i = i0 + tid * 4;
    float ga = gam[c] * rs, be = bet[c] - mu * ga;
    float4 v = *(const float4*)(g_pre + i);
    float4 o;
    o.x = fmaxf(fmaf(v.x, ga, be), 0.f);
    o.y = fmaxf(fmaf(v.y, ga, be), 0.f);
    o.z = fmaxf(fmaf(v.z, ga, be), 0.f);
    o.w = fmaxf(fmaf(v.w, ga, be), 0.f);
    *(float4*)(out + i) = o;
}

// -------------------------------------------------------------------------
extern "C" void kernel_launch(void* const* d_in, const int* in_sizes, int n_in,
                              void* d_out, int out_size) {
    const float* x        = (const float*)d_in[0];
    const float* w_off    = (const float*)d_in[1];
    const float* b_off    = (const float*)d_in[2];
    const float* g_gn_off = (const float*)d_in[3];
    const float* b_gn_off = (const float*)d_in[4];
    const float* w_dsc    = (const float*)d_in[5];
    const float* b_dsc    = (const float*)d_in[6];
    const float* g_gn     = (const float*)d_in[7];
    const float* b_gn     = (const float*)d_in[8];
    float* out = (float*)d_out;

    k_conv1<<<dim3(65, 4), 128>>>(x, w_off, b_off, w_dsc);
    k_gn1_stats<<<20, 256>>>();
    k_offsets<<<256, 256>>>(g_gn_off, b_gn_off);

    k_fused<<<dim3(128, 4), 128>>>(x, b_dsc);

    k_final<<<4096, 256>>>(g_gn, b_gn, out);
}

// round 10
// speedup vs baseline: 1.2884x; 1.2884x over previous
#include <cuda_runtime.h>

#define H 128
#define W 128
#define HW 16384

// ---------------- device scratch (no allocations allowed) ----------------
__device__ float g_off[4 * 10 * HW];       // conv1 output, channels 0..9 only
__device__ float g_mu[20];                 // GN1 mean  per (b, group0..4)
__device__ float g_rstd[20];               // GN1 rstd
__device__ float g_ymap[4 * 9 * HW];       // clipped y coordinate per (b,k,h,w)
__device__ float g_pre[4 * 64 * HW];       // conv2 output pre-GN
__device__ float g_part[4 * 128 * 16 * 2]; // per-(b,h,group) partial sum/sumsq
__device__ unsigned long long g_wD[576 * 64]; // conv2 weights, transposed AND
                                              // duplicated: g_wD[ci*9+k][co] = {w,w}

#define FMA2(a, v, wt) asm("fma.rn.f32x2 %0, %1, %2, %0;" : "+l"(a) : "l"(v), "l"(wt))

// ------- kernel 1: 3x3 conv 64->10ch, 2 rows/thread  (+ weight prep) -----
// grid (65, 4): bx<64 -> conv rows 2bx,2bx+1 ; bx==64 -> build g_wD
__global__ void __launch_bounds__(128) k_conv1(const float* __restrict__ x,
                                               const float* __restrict__ w_off,
                                               const float* __restrict__ b_off,
                                               const float* __restrict__ w_dsc) {
    int bx = blockIdx.x, b = blockIdx.y;
    int tid = threadIdx.x;

    if (bx == 64) {                        // weight transpose + f32x2 dup
        int t = b * 128 + tid;             // 0..511
        for (int i = t; i < 36864; i += 512) {
            int co = i / 576, r = i - co * 576;  // r = ci*9+k
            float wv = w_dsc[i];
            unsigned long long d;
            asm("mov.b64 %0,{%1,%1};" : "=l"(d) : "f"(wv));
            g_wD[r * 64 + co] = d;
        }
        return;
    }

    __shared__ float ws[64 * 90]; // [cin][t(9)][c(10)] channel pairs 8B aligned
    for (int i = tid; i < 64 * 90; i += 128) {
        int cin = i / 90, r = i - cin * 90;
        int t = r / 10, c = r - t * 10;
        ws[i] = w_off[(c * 64 + cin) * 9 + t];
    }
    __syncthreads();

    int h0 = bx * 2;                       // rows h0, h0+1
    int w = tid;

    unsigned long long acc0[5], acc1[5];
#pragma unroll
    for (int j = 0; j < 5; j++) {
        float b0 = b_off[2 * j], b1 = b_off[2 * j + 1];
        unsigned long long bb;
        asm("mov.b64 %0,{%1,%2};" : "=l"(bb) : "f"(b0), "f"(b1));
        acc0[j] = bb; acc1[j] = bb;
    }

    const float* xb = x + b * 64 * HW;
    for (int cin = 0; cin < 64; ++cin) {
        float r[4][3];                     // rows h0-1 .. h0+2
#pragma unroll
        for (int dy = 0; dy < 4; ++dy) {
            int hy = h0 - 1 + dy;
            bool hv = (hy >= 0 && hy < H);
            const float* row = xb + cin * HW + hy * W;
            r[dy][0] = (hv && w >= 1)       ? row[w - 1] : 0.f;
            r[dy][1] = hv                    ? row[w]     : 0.f;
            r[dy][2] = (hv && w <= W - 2)    ? row[w + 1] : 0.f;
        }
        const unsigned long long* wp2 = (const unsigned long long*)(ws + cin * 90);
#pragma unroll
        for (int t = 0; t < 9; t++) {
            int dy = t / 3, dx = t - dy * 3;
            unsigned long long v0, v1;
            asm("mov.b64 %0,{%1,%1};" : "=l"(v0) : "f"(r[dy][dx]));
            asm("mov.b64 %0,{%1,%1};" : "=l"(v1) : "f"(r[dy + 1][dx]));
#pragma unroll
            for (int j = 0; j < 5; j++) {
                unsigned long long wpair = wp2[t * 5 + j];
                FMA2(acc0[j], v0, wpair);
                FMA2(acc1[j], v1, wpair);
            }
        }
    }
    int base0 = b * 10 * HW + h0 * W + w;
#pragma unroll
    for (int j = 0; j < 5; j++) {
        union { unsigned long long u; float2 f; } c0, c1;
        c0.u = acc0[j]; c1.u = acc1[j];
        g_off[base0 + (2 * j) * HW]         = c0.f.x;
        g_off[base0 + (2 * j + 1) * HW]     = c0.f.y;
        g_off[base0 + W + (2 * j) * HW]     = c1.f.x;
        g_off[base0 + W + (2 * j + 1) * HW] = c1.f.y;
    }
}

// ---------------- kernel 2: GN1 stats (groups of 2 channels) -------------
__global__ void __launch_bounds__(256) k_gn1_stats() {
    int bg = blockIdx.x;          // 0..19 : b*5+g
    int b = bg / 5, g = bg - b * 5;
    const float* p = g_off + (b * 10 + 2 * g) * HW;
    float s = 0.f, q = 0.f;
    for (int i = threadIdx.x; i < 2 * HW; i += 256) {
        float v = p[i];
        s += v; q += v * v;
    }
    __shared__ float rs[256], rq[256];
    int tid = threadIdx.x;
    rs[tid] = s; rq[tid] = q;
    __syncthreads();
    for (int st = 128; st > 0; st >>= 1) {
        if (tid < st) { rs[tid] += rs[tid + st]; rq[tid] += rq[tid + st]; }
        __syncthreads();
    }
    if (tid == 0) {
        float mu = rs[0] / 32768.f;
        float var = rq[0] / 32768.f - mu * mu;
        g_mu[bg] = mu;
        g_rstd[bg] = rsqrtf(var + 1e-5f);
    }
}

// --------- kernel 3: normalize + tanh + cumsum -> y coordinate map -------
__global__ void __launch_bounds__(256) k_offsets(const float* __restrict__ gam,
                                                 const float* __restrict__ bet) {
    int pix = blockIdx.x * 256 + threadIdx.x;   // 65536 pixels
    int b = pix >> 14, hw = pix & 16383;
    int h = hw >> 7;

    float t[10];
#pragma unroll
    for (int c = 0; c < 10; c++) {
        float v = g_off[(b * 10 + c) * HW + hw];
        int g = c >> 1;
        v = (v - g_mu[b * 5 + g]) * g_rstd[b * 5 + g];
        t[c] = tanhf(v * gam[c] + bet[c]);
    }
    float yn[9];
    yn[3] = t[3];
    yn[2] = t[2] + yn[3];
    yn[1] = t[1] + yn[2];
    yn[0] = t[0] + yn[1];
    yn[4] = 0.f;
    yn[5] = t[5];
    yn[6] = yn[5] + t[6];
    yn[7] = yn[6] + t[7];
    yn[8] = yn[7] + t[8];
#pragma unroll
    for (int k = 0; k < 9; k++) {
        float yc = fminf(fmaxf((float)h + yn[k], 0.f), 127.f);
        g_ymap[((b * 9 + k) << 14) + hw] = yc;
    }
}

// --------- kernel 4: fused sampling + 9x1 strided conv (the big one) -----
// grid (h=128, b=4), 128 threads, 4 CTAs/SM -> whole grid in ONE wave.
// thread: oct = tid>>4 -> 8 output channels, wg = tid&15 -> 16 w.
// Chunks of 4 cin. Per chunk: cooperative fill of data slab (sampled values)
// AND duplicated-weight slab into smem; inner loop reads BOTH via LDS
// (weights broadcast across 16 threads -> 1 wavefront per LDS.128), so the
// per-thread LDG weight stream of round 5 (2304 LDG.128 -> L1tex bound)
// disappears entirely.
__global__ void __launch_bounds__(128, 4) k_fused(const float* __restrict__ x,
                                                  const float* __restrict__ b_dsc) {
    __shared__ float buf[4608];              // 4 x 1152 data slab (swizzled)
    __shared__ unsigned long long wsm[2304]; // 4ci x 9k x 64co dup'd weights
    __shared__ int2  tab[1152];              // packed sampling metadata
    __shared__ float redA[128], redB[128], qA[128], qB[128];
    // total: 18432 + 18432 + 9216 + 2048 = 48128 B

    int h = blockIdx.x, b = blockIdx.y;
    int tid = threadIdx.x;
    int oct = tid >> 4, wg = tid & 15;

    // phase A: pack metadata. Each thread writes/reads ONLY its own 9 entries
    // (e = tid + 128j), so no barrier needed around tab accesses.
    // entry: bits[0:14) addr0 = y0*128+xw, [14:25) sstore = k*128+swz(w),
    //        bit 25 = (y0 < 127), plus wy as float
    for (int e = tid; e < 1152; e += 128) {
        int k = e >> 7, w = e & 127;
        float yc = g_ymap[((b * 9 + k) << 14) + (h << 7) + w];
        int y0 = (int)yc;                    // yc in [0,127] -> trunc == floor
        float wy = yc - (float)y0;
        int xw = min(127, max(0, w + k - 4));
        int u = w >> 2;
        int sw = (((u ^ ((u >> 3) & 3)) << 2) | (w & 3));
        int pk = ((y0 << 7) + xw) | ((k * 128 + sw) << 14)
               | ((y0 < 127) ? (1 << 25) : 0);
        int2 t2; t2.x = pk; t2.y = __float_as_int(wy);
        tab[e] = t2;
    }

    unsigned long long acc[32];              // [co(8)][wpair(4)]
#pragma unroll
    for (int i = 0; i < 32; i++) acc[i] = 0ull;

    // swizzled 16B-line indices for this thread's 16 w
    int u0 = wg * 2;
    int su0 = u0 ^ ((u0 >> 3) & 3);
    int u1 = u0 + 1;
    int su1 = u1 ^ ((u1 >> 3) & 3);

#pragma unroll 1
    for (int c4 = 0; c4 < 16; ++c4) {        // cin chunks of 4
        __syncthreads();                     // previous GEMM done with smem

        // ---- fill data slab: s[ci][k][w] sampled (linear interp in y;
        //      x coord is exactly integer so wx == 0) ----
        const float* xb = x + ((b * 64 + c4 * 4) << 14);
        for (int e = tid; e < 1152; e += 128) {
            int2 pw = tab[e];
            int a0 = pw.x & 16383;
            int ss = (pw.x >> 14) & 2047;
            int dy = (pw.x >> 18) & 128;     // bit25 -> 0 or 128
            float wy = __int_as_float(pw.y);
            const float* p0 = xb + a0;
            const float* p1 = p0 + dy;
#pragma unroll
            for (int ci = 0; ci < 4; ci++) {
                float v0 = p0[ci << 14];
                float v1 = p1[ci << 14];
                buf[ss + ci * 1152] = fmaf(wy, v1 - v0, v0);
            }
        }

        // ---- fill weight slab: contiguous copy of this chunk's 2304 dup'd
        //      weights (rows r = c4*36 .. c4*36+35 of g_wD) ----
        {
            const ulonglong2* src = (const ulonglong2*)(g_wD + c4 * 2304);
            ulonglong2* dst = (ulonglong2*)wsm;
#pragma unroll
            for (int i = 0; i < 9; ++i)
                dst[tid + 128 * i] = src[tid + 128 * i];
        }
        __syncthreads();

        // ---- GEMM: 4 ci x 9 k, weights + data both from smem ----
#pragma unroll 1
        for (int cib = 0; cib < 4; ++cib) {
            const float* srow = buf + cib * 1152;
            const ulonglong2* wrow = (const ulonglong2*)wsm + cib * 288 + oct * 4;
#pragma unroll
            for (int k = 0; k < 9; ++k) {
                ulonglong2 wd0 = wrow[k * 32 + 0]; // co 8oct+0,+1
                ulonglong2 wd1 = wrow[k * 32 + 1]; // co +2,+3
                ulonglong2 wd2 = wrow[k * 32 + 2]; // co +4,+5
                ulonglong2 wd3 = wrow[k * 32 + 3]; // co +6,+7
                const ulonglong2* sk = (const ulonglong2*)(srow + k * 128);
                ulonglong2 va = sk[su0];
                ulonglong2 vb = sk[su1];
                FMA2(acc[0],  va.x, wd0.x); FMA2(acc[1],  va.y, wd0.x);
                FMA2(acc[2],  vb.x, wd0.x); FMA2(acc[3],  vb.y, wd0.x);
                FMA2(acc[4],  va.x, wd0.y); FMA2(acc[5],  va.y, wd0.y);
                FMA2(acc[6],  vb.x, wd0.y); FMA2(acc[7],  vb.y, wd0.y);
                FMA2(acc[8],  va.x, wd1.x); FMA2(acc[9],  va.y, wd1.x);
                FMA2(acc[10], vb.x, wd1.x); FMA2(acc[11], vb.y, wd1.x);
                FMA2(acc[12], va.x, wd1.y); FMA2(acc[13], va.y, wd1.y);
                FMA2(acc[14], vb.x, wd1.y); FMA2(acc[15], vb.y, wd1.y);
                FMA2(acc[16], va.x, wd2.x); FMA2(acc[17], va.y, wd2.x);
                FMA2(acc[18], vb.x, wd2.x); FMA2(acc[19], vb.y, wd2.x);
                FMA2(acc[20], va.x, wd2.y); FMA2(acc[21], va.y, wd2.y);
                FMA2(acc[22], vb.x, wd2.y); FMA2(acc[23], vb.y, wd2.y);
                FMA2(acc[24], va.x, wd3.x); FMA2(acc[25], va.y, wd3.x);
                FMA2(acc[26], vb.x, wd3.x); FMA2(acc[27], vb.y, wd3.x);
                FMA2(acc[28], va.x, wd3.y); FMA2(acc[29], va.y, wd3.y);
                FMA2(acc[30], vb.x, wd3.y); FMA2(acc[31], vb.y, wd3.y);
            }
        }
    }

    // epilogue: bias, store pre-GN, deterministic partial stats.
    // c 0..3 -> GN group 2*oct ; c 4..7 -> group 2*oct+1
    float sA = 0.f, qa = 0.f, sB = 0.f, qb = 0.f;
#pragma unroll
    for (int c = 0; c < 8; ++c) {
        int co = oct * 8 + c;
        float bias = b_dsc[co];
        float o[8];
#pragma unroll
        for (int p = 0; p < 4; ++p) {
            union { unsigned long long u; float2 f; } cv;
            cv.u = acc[c * 4 + p];
            o[2 * p]     = cv.f.x + bias;
            o[2 * p + 1] = cv.f.y + bias;
        }
        float* outp = g_pre + ((b * 64 + co) << 14) + (h << 7) + wg * 8;
        float4 s0; s0.x = o[0]; s0.y = o[1]; s0.z = o[2]; s0.w = o[3];
        float4 s1; s1.x = o[4]; s1.y = o[5]; s1.z = o[6]; s1.w = o[7];
        *(float4*)(outp) = s0;
        *(float4*)(outp + 4) = s1;
        float ls = 0.f, lq = 0.f;
#pragma unroll
        for (int p = 0; p < 8; ++p) { ls += o[p]; lq += o[p] * o[p]; }
        if (c < 4) { sA += ls; qa += lq; } else { sB += ls; qb += lq; }
    }
    redA[tid] = sA; redB[tid] = sB; qA[tid] = qa; qB[tid] = qb;
    __syncthreads();
    if (tid < 16) {                         // tid = group g; oct o = g>>1
        int o = tid >> 1;
        const float* rs = (tid & 1) ? redB : redA;
        const float* rq = (tid & 1) ? qB : qA;
        float ss = 0.f, qq = 0.f;
#pragma unroll
        for (int i = 0; i < 16; ++i) {
            ss += rs[o * 16 + i];
            qq += rq[o * 16 + i];
        }
        int idx = (((b << 7) + h) * 16 + tid) * 2;
        g_part[idx] = ss;
        g_part[idx + 1] = qq;
    }
}

// --------- kernel 5: GN2 reduce (per block, own group) + norm + relu -----
__global__ void __launch_bounds__(256) k_final(const float* __restrict__ gam,
                                               const float* __restrict__ bet,
                                               float* __restrict__ out) {
    int tid = threadIdx.x;
    int i0 = blockIdx.x * 1024;             // block covers 1024 floats (one b,c)
    int b = i0 >> 20;
    int c = (i0 >> 14) & 63;
    int g = c >> 2;

    // reduce this group's 128 per-h partials (deterministic fixed order)
    __shared__ float red[8];
    float s = 0.f, q = 0.f;
    if (tid < 128) {
        int idx = (((b << 7) + tid) * 16 + g) * 2;
        s = g_part[idx];
        q = g_part[idx + 1];
    }
#pragma unroll
    for (int o = 16; o; o >>= 1) {
        s += __shfl_down_sync(0xffffffffu, s, o);
        q += __shfl_down_sync(0xffffffffu, q, o);
    }
    if (tid < 128 && (tid & 31) == 0) {
        red[(tid >> 5) * 2] = s;
        red[(tid >> 5) * 2 + 1] = q;
    }
    __syncthreads();
    if (tid == 0) {
        float ss = red[0] + red[2] + red[4] + red[6];
        float qq = red[1] + red[3] + red[5] + red[7];
        float mu = ss / 65536.f;
        float var = qq / 65536.f - mu * mu;
        red[0] = mu;
        red[1] = rsqrtf(var + 1e-5f);
    }
    __syncthreads();
    float mu = red[0], rs = red[1];

    int i = i0 + tid * 4;
    float ga = gam[c] * rs, be = bet[c] - mu * ga;
    float4 v = *(const float4*)(g_pre + i);
    float4 o;
    o.x = fmaxf(fmaf(v.x, ga, be), 0.f);
    o.y = fmaxf(fmaf(v.y, ga, be), 0.f);
    o.z = fmaxf(fmaf(v.z, ga, be), 0.f);
    o.w = fmaxf(fmaf(v.w, ga, be), 0.f);
    *(float4*)(out + i) = o;
}

// -------------------------------------------------------------------------
extern "C" void kernel_launch(void* const* d_in, const int* in_sizes, int n_in,
                              void* d_out, int out_size) {
    const float* x        = (const float*)d_in[0];
    const float* w_off    = (const float*)d_in[1];
    const float* b_off    = (const float*)d_in[2];
    const float* g_gn_off = (const float*)d_in[3];
    const float* b_gn_off = (const float*)d_in[4];
    const float* w_dsc    = (const float*)d_in[5];
    const float* b_dsc    = (const float*)d_in[6];
    const float* g_gn     = (const float*)d_in[7];
    const float* b_gn     = (const float*)d_in[8];
    float* out = (float*)d_out;

    k_conv1<<<dim3(65, 4), 128>>>(x, w_off, b_off, w_dsc);
    k_gn1_stats<<<20, 256>>>();
    k_offsets<<<256, 256>>>(g_gn_off, b_gn_off);

    k_fused<<<dim3(128, 4), 128>>>(x, b_dsc);

    k_final<<<4096, 256>>>(g_gn, b_gn, out);
}